// round 6
// baseline (speedup 1.0000x reference)
#include <cuda_runtime.h>
#include <math.h>

// ---------------------------------------------------------------------------
// Scratch: xh projected to 8 channels, still at 256x256.  [8][8][256][256]
// ---------------------------------------------------------------------------
__device__ float g_xhp[8 * 8 * 256 * 256];

// ---------------------------------------------------------------------------
// Kernel 1: pre_project  xh[8,16,256,256] --(pre_w[8,16], pre_b[8])--> g_xhp
// ---------------------------------------------------------------------------
__global__ __launch_bounds__(256) void pre_kernel(const float* __restrict__ xh,
                                                  const float* __restrict__ pre_w,
                                                  const float* __restrict__ pre_b)
{
    __shared__ float w[128];
    __shared__ float bb[8];
    if (threadIdx.x < 128) w[threadIdx.x] = pre_w[threadIdx.x];
    if (threadIdx.x < 8)   bb[threadIdx.x] = pre_b[threadIdx.x];
    __syncthreads();

    int idx = blockIdx.x * 256 + threadIdx.x;   // grid exactly covers 8*65536
    int b   = idx >> 16;
    int pix = idx & 65535;
    const float* px = xh + (size_t)b * 16 * 65536 + pix;
    float in[16];
#pragma unroll
    for (int c = 0; c < 16; c++) in[c] = __ldg(px + (size_t)c * 65536);
#pragma unroll
    for (int o = 0; o < 8; o++) {
        float s = bb[o];
#pragma unroll
        for (int c = 0; c < 16; c++) s += w[o * 16 + c] * in[c];
        g_xhp[((size_t)b * 8 + o) * 65536 + pix] = s;
    }
}

// ---------------------------------------------------------------------------
// Kernel 2: fully fused branches + tail + residual.
// One block = 32x16 output tile, 512 threads, 1 pixel/thread.
// ---------------------------------------------------------------------------
__global__ __launch_bounds__(512, 1) void fused_kernel(
    const float* __restrict__ xl,        // [8,8,512,512]
    const float* __restrict__ mask,      // [8,1,512,512]
    const float* __restrict__ g_ln_w,    // [4,5]
    const float* __restrict__ g_ln_b,    // [4,5]
    const float* __restrict__ g_base_w,  // [4,5,3,3]
    const float* __restrict__ g_base_b,  // [4,5]
    const float* __restrict__ g_base_s,  // [4,5]
    const float* __restrict__ g_wt_w,    // [4,20,3,3]  ch = c*4+k
    const float* __restrict__ g_wt_s,    // [4,20]
    const float* __restrict__ g_pw_w,    // [4,5,5]
    const float* __restrict__ tail_ln_w, // [20]
    const float* __restrict__ tail_ln_b, // [20]
    const float* __restrict__ tail_w,    // [8,20]
    const float* __restrict__ tail_b,    // [8]
    const float* __restrict__ res_w,     // [8,9]
    const float* __restrict__ res_b,     // [8]
    float* __restrict__ out)             // [8,8,512,512]
{
    // ---- weights in smem -------------------------------------------------
    __shared__ float sLNW[20], sLNB[20];
    __shared__ float sBW[4][5][9];
    __shared__ float sBB[20], sBS[20];
    __shared__ float sWW[4][5][4][9];   // [br][c][k][tap]
    __shared__ float sWS[4][5][4];
    __shared__ float sPW[4][5][5];
    __shared__ float sTLW[20], sTLB[20];
    __shared__ float sTW[8][20];
    __shared__ float sTB[8];
    __shared__ float sRW[8][9];
    __shared__ float sRB[8];
    // ---- data tiles ------------------------------------------------------
    // S:   LN'd 5-channel concat, full-res halo tile  rows=16+4, cols=32+4
    // CX4: Haar subbands (LL,LH,HL,HH packed in float4), half-res 10x18
    // TAG: conv'd+scaled subbands for the 8x16 tile cells
    __shared__ float  S[5][20][36];
    __shared__ float4 CX4[5][10][18];
    __shared__ float4 TAG4[5][8][16];

    const int tid = threadIdx.x;

    for (int t = tid; t < 20; t += 512) {
        sLNW[t] = g_ln_w[t];  sLNB[t] = g_ln_b[t];
        sBB[t]  = g_base_b[t]; sBS[t] = g_base_s[t];
        sTLW[t] = tail_ln_w[t]; sTLB[t] = tail_ln_b[t];
    }
    for (int t = tid; t < 180; t += 512) ((float*)sBW)[t] = g_base_w[t];
    for (int t = tid; t < 720; t += 512) ((float*)sWW)[t] = g_wt_w[t];
    for (int t = tid; t < 80;  t += 512) ((float*)sWS)[t] = g_wt_s[t];
    for (int t = tid; t < 100; t += 512) ((float*)sPW)[t] = g_pw_w[t];
    for (int t = tid; t < 160; t += 512) ((float*)sTW)[t] = tail_w[t];
    for (int t = tid; t < 72;  t += 512) ((float*)sRW)[t] = res_w[t];
    if (tid < 8) { sTB[tid] = tail_b[tid]; sRB[tid] = res_b[tid]; }

    const int x0 = blockIdx.x * 32;
    const int y0 = blockIdx.y * 16;
    const int b  = blockIdx.z;
    const int tx = tid & 31;
    const int ty = tid >> 5;

    float acc[20];

#pragma unroll
    for (int br = 0; br < 4; br++) {
        __syncthreads();   // protect S/TAG reuse across branches

        // ---- phase 1: load + bilinear upsample + channel-LN into S ------
        for (int hp = tid; hp < 720; hp += 512) {
            int sr = hp / 36;
            int sc = hp - sr * 36;
            int y = y0 - 2 + sr, x = x0 - 2 + sc;
            float v0 = 0.f, v1 = 0.f, v2 = 0.f, v3 = 0.f, v4 = 0.f;
            if ((unsigned)y < 512u && (unsigned)x < 512u) {
                const float SC = (float)(255.0 / 511.0);
                float cy = (float)y * SC;
                int   iy = (int)cy; iy = iy > 254 ? 254 : iy;
                float fy = cy - (float)iy;
                float cxx = (float)x * SC;
                int   ix = (int)cxx; ix = ix > 254 ? 254 : ix;
                float fx = cxx - (float)ix;
                float w00 = (1.f - fy) * (1.f - fx);
                float w01 = (1.f - fy) * fx;
                float w10 = fy * (1.f - fx);
                float w11 = fy * fx;
                const float* p0 = g_xhp + (((size_t)b * 8 + 2 * br) * 256 + iy) * 256 + ix;
                const float* p1 = p0 + 65536;
                v0 = w00 * p0[0] + w01 * p0[1] + w10 * p0[256] + w11 * p0[257];
                v1 = w00 * p1[0] + w01 * p1[1] + w10 * p1[256] + w11 * p1[257];
                size_t xi = (((size_t)b * 8 + 2 * br) * 512 + y) * 512 + x;
                v2 = __ldg(xl + xi);
                v3 = __ldg(xl + xi + 262144);
                v4 = __ldg(mask + ((size_t)b * 512 + y) * 512 + x);
                // LayerNorm over the 5 channels
                float u = 0.2f * (v0 + v1 + v2 + v3 + v4);
                float d0 = v0 - u, d1 = v1 - u, d2 = v2 - u, d3 = v3 - u, d4 = v4 - u;
                float var = 0.2f * (d0 * d0 + d1 * d1 + d2 * d2 + d3 * d3 + d4 * d4);
                float inv = rsqrtf(var + 1e-6f);
                v0 = sLNW[br * 5 + 0] * (d0 * inv) + sLNB[br * 5 + 0];
                v1 = sLNW[br * 5 + 1] * (d1 * inv) + sLNB[br * 5 + 1];
                v2 = sLNW[br * 5 + 2] * (d2 * inv) + sLNB[br * 5 + 2];
                v3 = sLNW[br * 5 + 3] * (d3 * inv) + sLNB[br * 5 + 3];
                v4 = sLNW[br * 5 + 4] * (d4 * inv) + sLNB[br * 5 + 4];
            }
            S[0][sr][sc] = v0; S[1][sr][sc] = v1; S[2][sr][sc] = v2;
            S[3][sr][sc] = v3; S[4][sr][sc] = v4;
        }
        __syncthreads();

        // ---- phase 2: Haar DWT butterflies -> CX4 -----------------------
        for (int t = tid; t < 900; t += 512) {
            int c = t / 180; int cell = t - c * 180;
            int ci = cell / 18; int cj = cell - ci * 18;
            int sr = 2 * ci, sc = 2 * cj;
            float a = S[c][sr][sc],     e = S[c][sr][sc + 1];
            float f = S[c][sr + 1][sc], g = S[c][sr + 1][sc + 1];
            float s1 = a + e, dd1 = a - e, s2 = f + g, dd2 = f - g;
            CX4[c][ci][cj] = make_float4(0.5f * (s1 + s2),   // LL
                                         0.5f * (s1 - s2),   // LH
                                         0.5f * (dd1 + dd2), // HL
                                         0.5f * (dd1 - dd2));// HH
        }
        __syncthreads();

        // ---- phase 3: 3x3 conv on subbands, 4-cell quads -> TAG4 --------
        for (int t = tid; t < 640; t += 512) {
            int k  = t & 3;
            int r  = t >> 2;            // 0..159
            int qj = (r & 3) * 4;       // quad start col
            int ti = (r >> 2) & 7;
            int c  = r >> 5;            // 0..4
            float cxv[3][6];
#pragma unroll
            for (int dy = 0; dy < 3; dy++)
#pragma unroll
                for (int dx = 0; dx < 6; dx++)
                    cxv[dy][dx] = ((const float*)&CX4[c][ti + dy][qj + dx])[k];
            const float* wv = &sWW[0][0][0][0] + (((br * 5 + c) * 4) + k) * 9;
            float ws = sWS[br][c][k];
#pragma unroll
            for (int cc = 0; cc < 4; cc++) {
                float s = 0.f;
#pragma unroll
                for (int dy = 0; dy < 3; dy++)
#pragma unroll
                    for (int dx = 0; dx < 3; dx++)
                        s += wv[dy * 3 + dx] * cxv[dy][cc + dx];
                ((float*)&TAG4[c][ti][qj + cc])[k] = s * ws;
            }
        }
        __syncthreads();

        // ---- phase 4: base conv + iDWT + pointwise -> acc ---------------
        {
            float v[5];
            int ci = ty >> 1, cj = tx >> 1;
            int py = ty & 1,  px = tx & 1;
#pragma unroll
            for (int c = 0; c < 5; c++) {
                const float* wv = &sBW[0][0][0] + (br * 5 + c) * 9;
                float s = 0.f;
#pragma unroll
                for (int dy = 0; dy < 3; dy++)
#pragma unroll
                    for (int dx = 0; dx < 3; dx++)
                        s += wv[dy * 3 + dx] * S[c][ty + 1 + dy][tx + 1 + dx];
                s = (s + sBB[br * 5 + c]) * sBS[br * 5 + c];
                float4 tg = TAG4[c][ci][cj];
                float t1 = py ? -tg.y : tg.y;
                float t2 = px ? -tg.z : tg.z;
                float t3 = (py ^ px) ? -tg.w : tg.w;
                v[c] = s + 0.5f * (tg.x + t1 + t2 + t3);
            }
#pragma unroll
            for (int o = 0; o < 5; o++) {
                float s = 0.f;
#pragma unroll
                for (int c = 0; c < 5; c++) s += sPW[br][o][c] * v[c];
                acc[br * 5 + o] = s;
            }
        }
    }

    // ---- tail: LN(20) -> 20->8 matmul -> exact GELU, + residual ---------
    float u = 0.f;
#pragma unroll
    for (int j = 0; j < 20; j++) u += acc[j];
    u *= 0.05f;
    float var = 0.f;
#pragma unroll
    for (int j = 0; j < 20; j++) { float d = acc[j] - u; var += d * d; }
    var *= 0.05f;
    float inv = rsqrtf(var + 1e-6f);
#pragma unroll
    for (int j = 0; j < 20; j++) acc[j] = sTLW[j] * ((acc[j] - u) * inv) + sTLB[j];

    int y = y0 + ty, x = x0 + tx;
    size_t pix = (size_t)y * 512 + x;
    float xv[8];
#pragma unroll
    for (int c = 0; c < 8; c++)
        xv[c] = __ldg(xl + ((size_t)b * 8 + c) * 262144 + pix);
    float mv = __ldg(mask + (size_t)b * 262144 + pix);

#pragma unroll
    for (int o = 0; o < 8; o++) {
        float t = sTB[o];
#pragma unroll
        for (int j = 0; j < 20; j++) t += sTW[o][j] * acc[j];
        float gel = t * 0.5f * (1.f + erff(t * 0.70710678118654752f));
        float r = sRB[o];
#pragma unroll
        for (int c = 0; c < 8; c++) r += sRW[o][c] * xv[c];
        r += sRW[o][8] * mv;
        out[((size_t)b * 8 + o) * 262144 + pix] = gel + r;
    }
}

// ---------------------------------------------------------------------------
// kernel_launch
// Inputs (metadata order):
//  0 xh, 1 xl, 2 mask, 3 pre_w, 4 pre_b, 5 g_ln_w, 6 g_ln_b, 7 g_base_w,
//  8 g_base_b, 9 g_base_s, 10 g_wt_w, 11 g_wt_s, 12 g_pw_w, 13 tail_ln_w,
// 14 tail_ln_b, 15 tail_w, 16 tail_b, 17 res_w, 18 res_b
// ---------------------------------------------------------------------------
extern "C" void kernel_launch(void* const* d_in, const int* in_sizes, int n_in,
                              void* d_out, int out_size)
{
    (void)in_sizes; (void)n_in; (void)out_size;
    const float* xh        = (const float*)d_in[0];
    const float* xl        = (const float*)d_in[1];
    const float* mask      = (const float*)d_in[2];
    const float* pre_w     = (const float*)d_in[3];
    const float* pre_b     = (const float*)d_in[4];
    const float* g_ln_w    = (const float*)d_in[5];
    const float* g_ln_b    = (const float*)d_in[6];
    const float* g_base_w  = (const float*)d_in[7];
    const float* g_base_b  = (const float*)d_in[8];
    const float* g_base_s  = (const float*)d_in[9];
    const float* g_wt_w    = (const float*)d_in[10];
    const float* g_wt_s    = (const float*)d_in[11];
    const float* g_pw_w    = (const float*)d_in[12];
    const float* tail_ln_w = (const float*)d_in[13];
    const float* tail_ln_b = (const float*)d_in[14];
    const float* tail_w    = (const float*)d_in[15];
    const float* tail_b    = (const float*)d_in[16];
    const float* res_w     = (const float*)d_in[17];
    const float* res_b     = (const float*)d_in[18];
    float* out = (float*)d_out;

    pre_kernel<<<2048, 256>>>(xh, pre_w, pre_b);

    dim3 grid(512 / 32, 512 / 16, 8);   // 16 x 32 x 8 tiles
    fused_kernel<<<grid, 512>>>(xl, mask,
                                g_ln_w, g_ln_b, g_base_w, g_base_b, g_base_s,
                                g_wt_w, g_wt_s, g_pw_w,
                                tail_ln_w, tail_ln_b, tail_w, tail_b,
                                res_w, res_b, out);
}

// round 7
// speedup vs baseline: 1.1998x; 1.1998x over previous
#include <cuda_runtime.h>
#include <math.h>

// ---------------------------------------------------------------------------
// Scratch: xh projected to 8 channels, still at 256x256.  [8][8][256][256]
// ---------------------------------------------------------------------------
__device__ float g_xhp[8 * 8 * 256 * 256];

// ---------------------------------------------------------------------------
// Kernel 1: pre_project  xh[8,16,256,256] --(pre_w[8,16], pre_b[8])--> g_xhp
// ---------------------------------------------------------------------------
__global__ __launch_bounds__(256) void pre_kernel(const float* __restrict__ xh,
                                                  const float* __restrict__ pre_w,
                                                  const float* __restrict__ pre_b)
{
    __shared__ float w[128];
    __shared__ float bb[8];
    if (threadIdx.x < 128) w[threadIdx.x] = pre_w[threadIdx.x];
    if (threadIdx.x < 8)   bb[threadIdx.x] = pre_b[threadIdx.x];
    __syncthreads();

    int idx = blockIdx.x * 256 + threadIdx.x;   // grid exactly covers 8*65536
    int b   = idx >> 16;
    int pix = idx & 65535;
    const float* px = xh + (size_t)b * 16 * 65536 + pix;
    float in[16];
#pragma unroll
    for (int c = 0; c < 16; c++) in[c] = __ldg(px + (size_t)c * 65536);
#pragma unroll
    for (int o = 0; o < 8; o++) {
        float s = bb[o];
#pragma unroll
        for (int c = 0; c < 16; c++) s += w[o * 16 + c] * in[c];
        g_xhp[((size_t)b * 8 + o) * 65536 + pix] = s;
    }
}

// ---------------------------------------------------------------------------
// Kernel 2: fully fused branches + tail + residual.
// One block = 32x16 output tile, 512 threads, 1 pixel/thread.
// Forced to <=64 regs so 2 blocks / SM (50% occupancy).
// ---------------------------------------------------------------------------
__global__ __launch_bounds__(512, 2) void fused_kernel(
    const float* __restrict__ xl,        // [8,8,512,512]
    const float* __restrict__ mask,      // [8,1,512,512]
    const float* __restrict__ g_ln_w,    // [4,5]
    const float* __restrict__ g_ln_b,    // [4,5]
    const float* __restrict__ g_base_w,  // [4,5,3,3]
    const float* __restrict__ g_base_b,  // [4,5]
    const float* __restrict__ g_base_s,  // [4,5]
    const float* __restrict__ g_wt_w,    // [4,20,3,3]  ch = c*4+k
    const float* __restrict__ g_wt_s,    // [4,20]
    const float* __restrict__ g_pw_w,    // [4,5,5]
    const float* __restrict__ tail_ln_w, // [20]
    const float* __restrict__ tail_ln_b, // [20]
    const float* __restrict__ tail_w,    // [8,20]
    const float* __restrict__ tail_b,    // [8]
    const float* __restrict__ res_w,     // [8,9]
    const float* __restrict__ res_b,     // [8]
    float* __restrict__ out)             // [8,8,512,512]
{
    // ---- weights in smem -------------------------------------------------
    __shared__ float sLNW[20], sLNB[20];
    __shared__ float sBW[4][5][9];
    __shared__ float sBB[20], sBS[20];
    __shared__ float sWW[4][5][4][9];   // [br][c][k][tap]
    __shared__ float sWS[4][5][4];
    __shared__ float sPW[4][5][5];
    __shared__ float sTLW[20], sTLB[20];
    __shared__ float sTW[8][20];        // becomes TW' = tail_w * tail_ln_w
    __shared__ float sTB[8];
    __shared__ float sRW[8][9];
    __shared__ float sRB[8];
    __shared__ float sRS[8];            // row sums of TW'
    __shared__ float sC[8];             // folded LN-bias + tail bias
    // ---- data tiles ------------------------------------------------------
    __shared__ float  S[5][20][36];
    __shared__ float4 CX4[5][10][18];
    __shared__ float4 TAG4[5][8][16];

    const int tid = threadIdx.x;

    for (int t = tid; t < 20; t += 512) {
        sLNW[t] = g_ln_w[t];  sLNB[t] = g_ln_b[t];
        sBB[t]  = g_base_b[t]; sBS[t] = g_base_s[t];
        sTLW[t] = tail_ln_w[t]; sTLB[t] = tail_ln_b[t];
    }
    for (int t = tid; t < 180; t += 512) ((float*)sBW)[t] = g_base_w[t];
    for (int t = tid; t < 720; t += 512) ((float*)sWW)[t] = g_wt_w[t];
    for (int t = tid; t < 80;  t += 512) ((float*)sWS)[t] = g_wt_s[t];
    for (int t = tid; t < 100; t += 512) ((float*)sPW)[t] = g_pw_w[t];
    for (int t = tid; t < 160; t += 512) ((float*)sTW)[t] = tail_w[t];
    for (int t = tid; t < 72;  t += 512) ((float*)sRW)[t] = res_w[t];
    if (tid < 8) { sTB[tid] = tail_b[tid]; sRB[tid] = res_b[tid]; }
    __syncthreads();

    // fold LN scale/bias of the tail into the 20->8 matmul
    if (tid < 8) {
        float C = sTB[tid];
        float rs = 0.f;
#pragma unroll
        for (int j = 0; j < 20; j++) C += sTW[tid][j] * sTLB[j];
#pragma unroll
        for (int j = 0; j < 20; j++) {
            float w = sTW[tid][j] * sTLW[j];
            sTW[tid][j] = w;
            rs += w;
        }
        sRS[tid] = rs;
        sC[tid]  = C;
    }

    const int x0 = blockIdx.x * 32;
    const int y0 = blockIdx.y * 16;
    const int b  = blockIdx.z;
    const int tx = tid & 31;
    const int ty = tid >> 5;

    // streaming tail accumulators (replace acc[20])
    float p[8] = {0.f, 0.f, 0.f, 0.f, 0.f, 0.f, 0.f, 0.f};
    float s1 = 0.f, s2 = 0.f;

#pragma unroll 1
    for (int br = 0; br < 4; br++) {
        __syncthreads();   // protect S/CX/TAG reuse across branches (+derived w)

        // ---- phase 1: load + bilinear upsample + channel-LN into S ------
        for (int hp = tid; hp < 720; hp += 512) {
            int sr = hp / 36;
            int sc = hp - sr * 36;
            int y = y0 - 2 + sr, x = x0 - 2 + sc;
            float v0 = 0.f, v1 = 0.f, v2 = 0.f, v3 = 0.f, v4 = 0.f;
            if ((unsigned)y < 512u && (unsigned)x < 512u) {
                const float SC = (float)(255.0 / 511.0);
                float cy = (float)y * SC;
                int   iy = (int)cy; iy = iy > 254 ? 254 : iy;
                float fy = cy - (float)iy;
                float cxx = (float)x * SC;
                int   ix = (int)cxx; ix = ix > 254 ? 254 : ix;
                float fx = cxx - (float)ix;
                float w00 = (1.f - fy) * (1.f - fx);
                float w01 = (1.f - fy) * fx;
                float w10 = fy * (1.f - fx);
                float w11 = fy * fx;
                const float* p0 = g_xhp + (((size_t)b * 8 + 2 * br) * 256 + iy) * 256 + ix;
                const float* p1 = p0 + 65536;
                v0 = w00 * p0[0] + w01 * p0[1] + w10 * p0[256] + w11 * p0[257];
                v1 = w00 * p1[0] + w01 * p1[1] + w10 * p1[256] + w11 * p1[257];
                size_t xi = (((size_t)b * 8 + 2 * br) * 512 + y) * 512 + x;
                v2 = __ldg(xl + xi);
                v3 = __ldg(xl + xi + 262144);
                v4 = __ldg(mask + ((size_t)b * 512 + y) * 512 + x);
                // LayerNorm over the 5 channels
                float u = 0.2f * (v0 + v1 + v2 + v3 + v4);
                float d0 = v0 - u, d1 = v1 - u, d2 = v2 - u, d3 = v3 - u, d4 = v4 - u;
                float var = 0.2f * (d0 * d0 + d1 * d1 + d2 * d2 + d3 * d3 + d4 * d4);
                float inv = rsqrtf(var + 1e-6f);
                v0 = sLNW[br * 5 + 0] * (d0 * inv) + sLNB[br * 5 + 0];
                v1 = sLNW[br * 5 + 1] * (d1 * inv) + sLNB[br * 5 + 1];
                v2 = sLNW[br * 5 + 2] * (d2 * inv) + sLNB[br * 5 + 2];
                v3 = sLNW[br * 5 + 3] * (d3 * inv) + sLNB[br * 5 + 3];
                v4 = sLNW[br * 5 + 4] * (d4 * inv) + sLNB[br * 5 + 4];
            }
            S[0][sr][sc] = v0; S[1][sr][sc] = v1; S[2][sr][sc] = v2;
            S[3][sr][sc] = v3; S[4][sr][sc] = v4;
        }
        __syncthreads();

        // ---- phase 2: Haar DWT butterflies -> CX4 -----------------------
        for (int t = tid; t < 900; t += 512) {
            int c = t / 180; int cell = t - c * 180;
            int ci = cell / 18; int cj = cell - ci * 18;
            int sr = 2 * ci, sc = 2 * cj;
            float2 r0 = *(const float2*)&S[c][sr][sc];
            float2 r1 = *(const float2*)&S[c][sr + 1][sc];
            float su1 = r0.x + r0.y, dd1 = r0.x - r0.y;
            float su2 = r1.x + r1.y, dd2 = r1.x - r1.y;
            CX4[c][ci][cj] = make_float4(0.5f * (su1 + su2),   // LL
                                         0.5f * (su1 - su2),   // LH
                                         0.5f * (dd1 + dd2),   // HL
                                         0.5f * (dd1 - dd2));  // HH
        }
        __syncthreads();

        // ---- phase 3: 3x3 conv on subbands, 4-cell quads -> TAG4 --------
        for (int t = tid; t < 640; t += 512) {
            int k  = t & 3;
            int r  = t >> 2;            // 0..159
            int qj = (r & 3) * 4;       // quad start col
            int ti = (r >> 2) & 7;
            int c  = r >> 5;            // 0..4
            float cxv[3][6];
#pragma unroll
            for (int dy = 0; dy < 3; dy++)
#pragma unroll
                for (int dx = 0; dx < 6; dx++)
                    cxv[dy][dx] = ((const float*)&CX4[c][ti + dy][qj + dx])[k];
            const float* wv = &sWW[0][0][0][0] + (((br * 5 + c) * 4) + k) * 9;
            float ws = sWS[br][c][k];
#pragma unroll
            for (int cc = 0; cc < 4; cc++) {
                float s = 0.f;
#pragma unroll
                for (int dy = 0; dy < 3; dy++)
#pragma unroll
                    for (int dx = 0; dx < 3; dx++)
                        s += wv[dy * 3 + dx] * cxv[dy][cc + dx];
                ((float*)&TAG4[c][ti][qj + cc])[k] = s * ws;
            }
        }
        __syncthreads();

        // ---- phase 4: base conv + iDWT + pointwise -> stream into tail --
        {
            int ci = ty >> 1, cj = tx >> 1;
            int py = ty & 1,  px = tx & 1;
            float o5[5] = {0.f, 0.f, 0.f, 0.f, 0.f};
#pragma unroll
            for (int c = 0; c < 5; c++) {
                const float* wv = &sBW[0][0][0] + (br * 5 + c) * 9;
                float s = 0.f;
#pragma unroll
                for (int dy = 0; dy < 3; dy++)
#pragma unroll
                    for (int dx = 0; dx < 3; dx++)
                        s += wv[dy * 3 + dx] * S[c][ty + 1 + dy][tx + 1 + dx];
                s = (s + sBB[br * 5 + c]) * sBS[br * 5 + c];
                float4 tg = TAG4[c][ci][cj];
                float t1 = py ? -tg.y : tg.y;
                float t2 = px ? -tg.z : tg.z;
                float t3 = (py ^ px) ? -tg.w : tg.w;
                float vc = s + 0.5f * (tg.x + t1 + t2 + t3);
#pragma unroll
                for (int o = 0; o < 5; o++) o5[o] += sPW[br][o][c] * vc;
            }
#pragma unroll
            for (int jj = 0; jj < 5; jj++) {
                float v = o5[jj];
                s1 += v;
                s2 += v * v;
#pragma unroll
                for (int o = 0; o < 8; o++) p[o] += sTW[o][br * 5 + jj] * v;
            }
        }
    }

    // ---- tail: folded LN(20)+matmul -> exact GELU, + residual -----------
    float u   = s1 * 0.05f;
    float var = fmaxf(s2 * 0.05f - u * u, 0.f);
    float inv = rsqrtf(var + 1e-6f);

    int y = y0 + ty, x = x0 + tx;
    size_t pix = (size_t)y * 512 + x;
    float xv[8];
#pragma unroll
    for (int c = 0; c < 8; c++)
        xv[c] = __ldg(xl + ((size_t)b * 8 + c) * 262144 + pix);
    float mv = __ldg(mask + (size_t)b * 262144 + pix);

#pragma unroll
    for (int o = 0; o < 8; o++) {
        float t = inv * (p[o] - u * sRS[o]) + sC[o];
        float gel = t * 0.5f * (1.f + erff(t * 0.70710678118654752f));
        float r = sRB[o];
#pragma unroll
        for (int c = 0; c < 8; c++) r += sRW[o][c] * xv[c];
        r += sRW[o][8] * mv;
        out[((size_t)b * 8 + o) * 262144 + pix] = gel + r;
    }
}

// ---------------------------------------------------------------------------
// kernel_launch
// Inputs (metadata order):
//  0 xh, 1 xl, 2 mask, 3 pre_w, 4 pre_b, 5 g_ln_w, 6 g_ln_b, 7 g_base_w,
//  8 g_base_b, 9 g_base_s, 10 g_wt_w, 11 g_wt_s, 12 g_pw_w, 13 tail_ln_w,
// 14 tail_ln_b, 15 tail_w, 16 tail_b, 17 res_w, 18 res_b
// ---------------------------------------------------------------------------
extern "C" void kernel_launch(void* const* d_in, const int* in_sizes, int n_in,
                              void* d_out, int out_size)
{
    (void)in_sizes; (void)n_in; (void)out_size;
    const float* xh        = (const float*)d_in[0];
    const float* xl        = (const float*)d_in[1];
    const float* mask      = (const float*)d_in[2];
    const float* pre_w     = (const float*)d_in[3];
    const float* pre_b     = (const float*)d_in[4];
    const float* g_ln_w    = (const float*)d_in[5];
    const float* g_ln_b    = (const float*)d_in[6];
    const float* g_base_w  = (const float*)d_in[7];
    const float* g_base_b  = (const float*)d_in[8];
    const float* g_base_s  = (const float*)d_in[9];
    const float* g_wt_w    = (const float*)d_in[10];
    const float* g_wt_s    = (const float*)d_in[11];
    const float* g_pw_w    = (const float*)d_in[12];
    const float* tail_ln_w = (const float*)d_in[13];
    const float* tail_ln_b = (const float*)d_in[14];
    const float* tail_w    = (const float*)d_in[15];
    const float* tail_b    = (const float*)d_in[16];
    const float* res_w     = (const float*)d_in[17];
    const float* res_b     = (const float*)d_in[18];
    float* out = (float*)d_out;

    pre_kernel<<<2048, 256>>>(xh, pre_w, pre_b);

    dim3 grid(512 / 32, 512 / 16, 8);   // 16 x 32 x 8 tiles
    fused_kernel<<<grid, 512>>>(xl, mask,
                                g_ln_w, g_ln_b, g_base_w, g_base_b, g_base_s,
                                g_wt_w, g_wt_s, g_pw_w,
                                tail_ln_w, tail_ln_b, tail_w, tail_b,
                                res_w, res_b, out);
}

// round 8
// speedup vs baseline: 1.6001x; 1.3337x over previous
#include <cuda_runtime.h>
#include <math.h>

// ---------------------------------------------------------------------------
// Constant-bank weight layout (floats). All compile-time-indexed weights get
// folded into FFMA operands by ptxas (no load instructions at all).
// ---------------------------------------------------------------------------
#define OFF_LNW  0      // [4][5]
#define OFF_LNB  20     // [4][5]
#define OFF_BW   40     // [4][5][9]
#define OFF_BB   220    // [4][5]
#define OFF_BS   240    // [4][5]
#define OFF_WW   260    // [4][5][4][9]  (runtime-indexed -> kept in smem too)
#define OFF_WS   980    // [4][5][4]
#define OFF_PW   1060   // [4][5][5]
#define OFF_TLW  1160   // [20]
#define OFF_TLB  1180   // [20]
#define OFF_TW   1200   // [8][20]
#define OFF_TB   1360   // [8]
#define OFF_RW   1368   // [8][9]
#define OFF_RB   1440   // [8]
#define OFF_PREW 1448   // [8][16]
#define OFF_PREB 1576   // [8]
#define W_TOTAL  1584

__constant__ float cW[W_TOTAL];
__device__ float g_wpack[W_TOTAL];

// Scratch: xh projected to 8 channels, still 256x256.  [8][8][256][256]
__device__ float g_xhp[8 * 8 * 256 * 256];

// ---------------------------------------------------------------------------
// pack_kernel: gather all weight arrays into g_wpack (one memcpy -> cW).
// ---------------------------------------------------------------------------
__global__ __launch_bounds__(256) void pack_kernel(
    const float* __restrict__ lnw, const float* __restrict__ lnb,
    const float* __restrict__ bw,  const float* __restrict__ bb,
    const float* __restrict__ bs,  const float* __restrict__ ww,
    const float* __restrict__ ws,  const float* __restrict__ pw,
    const float* __restrict__ tlw, const float* __restrict__ tlb,
    const float* __restrict__ tw,  const float* __restrict__ tb,
    const float* __restrict__ rw,  const float* __restrict__ rb,
    const float* __restrict__ prew, const float* __restrict__ preb)
{
    int i = blockIdx.x * 256 + threadIdx.x;
    if (i >= W_TOTAL) return;
    float v;
    if      (i < OFF_LNB)  v = lnw[i - OFF_LNW];
    else if (i < OFF_BW)   v = lnb[i - OFF_LNB];
    else if (i < OFF_BB)   v = bw[i - OFF_BW];
    else if (i < OFF_BS)   v = bb[i - OFF_BB];
    else if (i < OFF_WW)   v = bs[i - OFF_BS];
    else if (i < OFF_WS)   v = ww[i - OFF_WW];
    else if (i < OFF_PW)   v = ws[i - OFF_WS];
    else if (i < OFF_TLW)  v = pw[i - OFF_PW];
    else if (i < OFF_TLB)  v = tlw[i - OFF_TLW];
    else if (i < OFF_TW)   v = tlb[i - OFF_TLB];
    else if (i < OFF_TB)   v = tw[i - OFF_TW];
    else if (i < OFF_RW)   v = tb[i - OFF_TB];
    else if (i < OFF_RB)   v = rw[i - OFF_RW];
    else if (i < OFF_PREW) v = rb[i - OFF_RB];
    else if (i < OFF_PREB) v = prew[i - OFF_PREW];
    else                   v = preb[i - OFF_PREB];
    g_wpack[i] = v;
}

// ---------------------------------------------------------------------------
// Kernel 1: pre_project  xh[8,16,256,256] -> g_xhp  (weights folded from cW)
// ---------------------------------------------------------------------------
__global__ __launch_bounds__(256) void pre_kernel(const float* __restrict__ xh)
{
    int idx = blockIdx.x * 256 + threadIdx.x;   // covers 8*65536 exactly
    int b   = idx >> 16;
    int pix = idx & 65535;
    const float* px = xh + (size_t)b * 16 * 65536 + pix;
    float in[16];
#pragma unroll
    for (int c = 0; c < 16; c++) in[c] = __ldg(px + (size_t)c * 65536);
#pragma unroll
    for (int o = 0; o < 8; o++) {
        float s = cW[OFF_PREB + o];
#pragma unroll
        for (int c = 0; c < 16; c++) s += cW[OFF_PREW + o * 16 + c] * in[c];
        g_xhp[((size_t)b * 8 + o) * 65536 + pix] = s;
    }
}

// ---------------------------------------------------------------------------
// Per-branch body: all weight indices are compile-time via template BR,
// except the wavelet conv weights (runtime c,kp) which live in smem.
// ---------------------------------------------------------------------------
template<int BR>
__device__ __forceinline__ void do_branch(
    int tid, int x0, int y0, int b,
    const float* __restrict__ xl, const float* __restrict__ mask,
    float (&S)[5][20][36], float4 (&CX4)[5][10][18], float4 (&TAG4)[5][8][16],
    const float* __restrict__ sWW, const float* __restrict__ sWS,
    float* p, float& s1, float& s2)
{
    __syncthreads();   // protect S/CX/TAG reuse across branches

    // ---- phase 1: load + bilinear upsample + channel-LN into S ----------
    for (int hp = tid; hp < 720; hp += 512) {
        int sr = hp / 36;
        int sc = hp - sr * 36;
        int y = y0 - 2 + sr, x = x0 - 2 + sc;
        float v0 = 0.f, v1 = 0.f, v2 = 0.f, v3 = 0.f, v4 = 0.f;
        if ((unsigned)y < 512u && (unsigned)x < 512u) {
            const float SC = (float)(255.0 / 511.0);
            float cy = (float)y * SC;
            int   iy = (int)cy; iy = iy > 254 ? 254 : iy;
            float fy = cy - (float)iy;
            float cxx = (float)x * SC;
            int   ix = (int)cxx; ix = ix > 254 ? 254 : ix;
            float fx = cxx - (float)ix;
            float w00 = (1.f - fy) * (1.f - fx);
            float w01 = (1.f - fy) * fx;
            float w10 = fy * (1.f - fx);
            float w11 = fy * fx;
            const float* p0 = g_xhp + (((size_t)b * 8 + 2 * BR) * 256 + iy) * 256 + ix;
            const float* p1 = p0 + 65536;
            v0 = w00 * p0[0] + w01 * p0[1] + w10 * p0[256] + w11 * p0[257];
            v1 = w00 * p1[0] + w01 * p1[1] + w10 * p1[256] + w11 * p1[257];
            size_t xi = (((size_t)b * 8 + 2 * BR) * 512 + y) * 512 + x;
            v2 = __ldg(xl + xi);
            v3 = __ldg(xl + xi + 262144);
            v4 = __ldg(mask + ((size_t)b * 512 + y) * 512 + x);
            float u = 0.2f * (v0 + v1 + v2 + v3 + v4);
            float d0 = v0 - u, d1 = v1 - u, d2 = v2 - u, d3 = v3 - u, d4 = v4 - u;
            float var = 0.2f * (d0 * d0 + d1 * d1 + d2 * d2 + d3 * d3 + d4 * d4);
            float inv = rsqrtf(var + 1e-6f);
            v0 = cW[OFF_LNW + BR * 5 + 0] * (d0 * inv) + cW[OFF_LNB + BR * 5 + 0];
            v1 = cW[OFF_LNW + BR * 5 + 1] * (d1 * inv) + cW[OFF_LNB + BR * 5 + 1];
            v2 = cW[OFF_LNW + BR * 5 + 2] * (d2 * inv) + cW[OFF_LNB + BR * 5 + 2];
            v3 = cW[OFF_LNW + BR * 5 + 3] * (d3 * inv) + cW[OFF_LNB + BR * 5 + 3];
            v4 = cW[OFF_LNW + BR * 5 + 4] * (d4 * inv) + cW[OFF_LNB + BR * 5 + 4];
        }
        S[0][sr][sc] = v0; S[1][sr][sc] = v1; S[2][sr][sc] = v2;
        S[3][sr][sc] = v3; S[4][sr][sc] = v4;
    }
    __syncthreads();

    // ---- phase 2: Haar DWT butterflies -> CX4 ---------------------------
    for (int t = tid; t < 900; t += 512) {
        int c = t / 180; int cell = t - c * 180;
        int ci = cell / 18; int cj = cell - ci * 18;
        int sr = 2 * ci, sc = 2 * cj;
        float2 r0 = *(const float2*)&S[c][sr][sc];
        float2 r1 = *(const float2*)&S[c][sr + 1][sc];
        float su1 = r0.x + r0.y, dd1 = r0.x - r0.y;
        float su2 = r1.x + r1.y, dd2 = r1.x - r1.y;
        CX4[c][ci][cj] = make_float4(0.5f * (su1 + su2),   // LL
                                     0.5f * (su1 - su2),   // LH
                                     0.5f * (dd1 + dd2),   // HL
                                     0.5f * (dd1 - dd2));  // HH
    }
    __syncthreads();

    // ---- phase 3: 3x3 conv on subband pairs, 4-cell quads -> TAG4 -------
    // item = (c, ti, quad, kp): kp selects float2 half of each float4 cell.
    if (tid < 320) {
        int c  = tid >> 6;          // 0..4
        int r  = tid & 63;
        int kp = r & 1;             // subband pair: (2kp, 2kp+1)
        int qj = ((r >> 1) & 3) * 4;
        int ti = r >> 3;            // 0..7
        const float* wv = sWW + (((BR * 5 + c) * 4) + 2 * kp) * 9; // [k][9],[k+1][9]
        float a0[4] = {0.f, 0.f, 0.f, 0.f};
        float a1[4] = {0.f, 0.f, 0.f, 0.f};
#pragma unroll
        for (int dy = 0; dy < 3; dy++) {
            float2 row[6];
#pragma unroll
            for (int dx = 0; dx < 6; dx++)
                row[dx] = ((const float2*)&CX4[c][ti + dy][qj + dx])[kp];
#pragma unroll
            for (int dx = 0; dx < 3; dx++) {
                float w0 = wv[dy * 3 + dx];
                float w1 = wv[9 + dy * 3 + dx];
#pragma unroll
                for (int cc = 0; cc < 4; cc++) {
                    a0[cc] += w0 * row[cc + dx].x;
                    a1[cc] += w1 * row[cc + dx].y;
                }
            }
        }
        float ws0 = sWS[(BR * 5 + c) * 4 + 2 * kp];
        float ws1 = sWS[(BR * 5 + c) * 4 + 2 * kp + 1];
#pragma unroll
        for (int cc = 0; cc < 4; cc++)
            ((float2*)&TAG4[c][ti][qj + cc])[kp] = make_float2(a0[cc] * ws0, a1[cc] * ws1);
    }
    __syncthreads();

    // ---- phase 4: base conv + iDWT + pointwise -> stream into tail ------
    {
        int tx = tid & 31, ty = tid >> 5;
        int ci = ty >> 1, cj = tx >> 1;
        int py = ty & 1,  px = tx & 1;
        float o5[5] = {0.f, 0.f, 0.f, 0.f, 0.f};
#pragma unroll
        for (int c = 0; c < 5; c++) {
            float s = 0.f;
#pragma unroll
            for (int dy = 0; dy < 3; dy++)
#pragma unroll
                for (int dx = 0; dx < 3; dx++)
                    s += cW[OFF_BW + (BR * 5 + c) * 9 + dy * 3 + dx]
                         * S[c][ty + 1 + dy][tx + 1 + dx];
            s = (s + cW[OFF_BB + BR * 5 + c]) * cW[OFF_BS + BR * 5 + c];
            float4 tg = TAG4[c][ci][cj];
            float t1 = py ? -tg.y : tg.y;
            float t2 = px ? -tg.z : tg.z;
            float t3 = (py ^ px) ? -tg.w : tg.w;
            float vc = s + 0.5f * (tg.x + t1 + t2 + t3);
#pragma unroll
            for (int o = 0; o < 5; o++)
                o5[o] += cW[OFF_PW + BR * 25 + o * 5 + c] * vc;
        }
#pragma unroll
        for (int jj = 0; jj < 5; jj++) {
            float v = o5[jj];
            s1 += v;
            s2 += v * v;
            float vs = cW[OFF_TLW + BR * 5 + jj] * v;   // fold tail-LN scale
#pragma unroll
            for (int o = 0; o < 8; o++)
                p[o] += cW[OFF_TW + o * 20 + BR * 5 + jj] * vs;
        }
    }
}

// ---------------------------------------------------------------------------
// Kernel 2: fused branches + tail + residual. 32x16 tile, 512 thr, 1 px/thr.
// ---------------------------------------------------------------------------
__global__ __launch_bounds__(512, 2) void fused_kernel(
    const float* __restrict__ xl,        // [8,8,512,512]
    const float* __restrict__ mask,      // [8,1,512,512]
    const float* __restrict__ g_wt_w,    // [4,20,3,3] (smem copy: runtime idx)
    const float* __restrict__ g_wt_s,    // [4,20]
    float* __restrict__ out)             // [8,8,512,512]
{
    __shared__ float sWW[720];
    __shared__ float sWS[80];
    __shared__ float sRS[8];             // row sums of folded tail matrix
    __shared__ float sC[8];              // folded LN-bias + tail bias
    __shared__ float  S[5][20][36];
    __shared__ float4 CX4[5][10][18];
    __shared__ float4 TAG4[5][8][16];

    const int tid = threadIdx.x;
    for (int t = tid; t < 720; t += 512) sWW[t] = g_wt_w[t];
    for (int t = tid; t < 80;  t += 512) sWS[t] = g_wt_s[t];
    if (tid < 8) {
        float rs = 0.f, C = cW[OFF_TB + tid];
#pragma unroll
        for (int j = 0; j < 20; j++) {
            float w = cW[OFF_TW + tid * 20 + j];
            rs += w * cW[OFF_TLW + j];
            C  += w * cW[OFF_TLB + j];
        }
        sRS[tid] = rs;
        sC[tid]  = C;
    }

    const int x0 = blockIdx.x * 32;
    const int y0 = blockIdx.y * 16;
    const int b  = blockIdx.z;

    float p[8] = {0.f, 0.f, 0.f, 0.f, 0.f, 0.f, 0.f, 0.f};
    float s1 = 0.f, s2 = 0.f;

    do_branch<0>(tid, x0, y0, b, xl, mask, S, CX4, TAG4, sWW, sWS, p, s1, s2);
    do_branch<1>(tid, x0, y0, b, xl, mask, S, CX4, TAG4, sWW, sWS, p, s1, s2);
    do_branch<2>(tid, x0, y0, b, xl, mask, S, CX4, TAG4, sWW, sWS, p, s1, s2);
    do_branch<3>(tid, x0, y0, b, xl, mask, S, CX4, TAG4, sWW, sWS, p, s1, s2);

    // ---- tail: folded LN(20)+matmul -> exact GELU, + residual -----------
    float u   = s1 * 0.05f;
    float var = fmaxf(s2 * 0.05f - u * u, 0.f);
    float inv = rsqrtf(var + 1e-6f);

    const int tx = tid & 31, ty = tid >> 5;
    int y = y0 + ty, x = x0 + tx;
    size_t pix = (size_t)y * 512 + x;
    float xv[8];
#pragma unroll
    for (int c = 0; c < 8; c++)
        xv[c] = __ldg(xl + ((size_t)b * 8 + c) * 262144 + pix);
    float mv = __ldg(mask + (size_t)b * 262144 + pix);

#pragma unroll
    for (int o = 0; o < 8; o++) {
        float t = inv * (p[o] - u * sRS[o]) + sC[o];
        float gel = t * 0.5f * (1.f + erff(t * 0.70710678118654752f));
        float r = cW[OFF_RB + o];
#pragma unroll
        for (int c = 0; c < 8; c++) r += cW[OFF_RW + o * 9 + c] * xv[c];
        r += cW[OFF_RW + o * 9 + 8] * mv;
        out[((size_t)b * 8 + o) * 262144 + pix] = gel + r;
    }
}

// ---------------------------------------------------------------------------
// kernel_launch
// Inputs: 0 xh, 1 xl, 2 mask, 3 pre_w, 4 pre_b, 5 g_ln_w, 6 g_ln_b,
//  7 g_base_w, 8 g_base_b, 9 g_base_s, 10 g_wt_w, 11 g_wt_s, 12 g_pw_w,
// 13 tail_ln_w, 14 tail_ln_b, 15 tail_w, 16 tail_b, 17 res_w, 18 res_b
// ---------------------------------------------------------------------------
extern "C" void kernel_launch(void* const* d_in, const int* in_sizes, int n_in,
                              void* d_out, int out_size)
{
    (void)in_sizes; (void)n_in; (void)out_size;
    const float* xh   = (const float*)d_in[0];
    const float* xl   = (const float*)d_in[1];
    const float* mask = (const float*)d_in[2];
    float* out = (float*)d_out;

    pack_kernel<<<(W_TOTAL + 255) / 256, 256>>>(
        (const float*)d_in[5],  (const float*)d_in[6],
        (const float*)d_in[7],  (const float*)d_in[8],
        (const float*)d_in[9],  (const float*)d_in[10],
        (const float*)d_in[11], (const float*)d_in[12],
        (const float*)d_in[13], (const float*)d_in[14],
        (const float*)d_in[15], (const float*)d_in[16],
        (const float*)d_in[17], (const float*)d_in[18],
        (const float*)d_in[3],  (const float*)d_in[4]);

    void* wpack_ptr = nullptr;
    cudaGetSymbolAddress(&wpack_ptr, g_wpack);
    cudaMemcpyToSymbolAsync(cW, wpack_ptr, W_TOTAL * sizeof(float), 0,
                            cudaMemcpyDeviceToDevice, 0);

    pre_kernel<<<2048, 256>>>(xh);

    dim3 grid(512 / 32, 512 / 16, 8);   // 16 x 32 x 8 tiles
    fused_kernel<<<grid, 512>>>(xl, mask,
                                (const float*)d_in[10], (const float*)d_in[11],
                                out);
}

// round 9
// speedup vs baseline: 1.9861x; 1.2412x over previous
#include <cuda_runtime.h>
#include <math.h>

// ---------------------------------------------------------------------------
// Constant-bank weight layout (floats). All compile-time-indexed weights get
// folded into FFMA operands by ptxas (no load instructions at all).
// ---------------------------------------------------------------------------
#define OFF_LNW  0      // [4][5]
#define OFF_LNB  20     // [4][5]
#define OFF_BW   40     // [4][5][9]
#define OFF_BB   220    // [4][5]
#define OFF_BS   240    // [4][5]
#define OFF_WW   260    // [4][5][4][9]  (runtime-indexed -> kept in smem too)
#define OFF_WS   980    // [4][5][4]
#define OFF_PW   1060   // [4][5][5]
#define OFF_TLW  1160   // [20]
#define OFF_TLB  1180   // [20]
#define OFF_TW   1200   // [8][20]
#define OFF_TB   1360   // [8]
#define OFF_RW   1368   // [8][9]
#define OFF_RB   1440   // [8]
#define OFF_PREW 1448   // [8][16]
#define OFF_PREB 1576   // [8]
#define W_TOTAL  1584

__constant__ float cW[W_TOTAL];
__device__ float g_wpack[W_TOTAL];

// Scratch: xh projected to 8 channels, still 256x256.  [8][8][256][256]
__device__ float g_xhp[8 * 8 * 256 * 256];

// ---------------------------------------------------------------------------
// pack_kernel: gather all weight arrays into g_wpack (one memcpy -> cW).
// ---------------------------------------------------------------------------
__global__ __launch_bounds__(256) void pack_kernel(
    const float* __restrict__ lnw, const float* __restrict__ lnb,
    const float* __restrict__ bw,  const float* __restrict__ bb,
    const float* __restrict__ bs,  const float* __restrict__ ww,
    const float* __restrict__ ws,  const float* __restrict__ pw,
    const float* __restrict__ tlw, const float* __restrict__ tlb,
    const float* __restrict__ tw,  const float* __restrict__ tb,
    const float* __restrict__ rw,  const float* __restrict__ rb,
    const float* __restrict__ prew, const float* __restrict__ preb)
{
    int i = blockIdx.x * 256 + threadIdx.x;
    if (i >= W_TOTAL) return;
    float v;
    if      (i < OFF_LNB)  v = lnw[i - OFF_LNW];
    else if (i < OFF_BW)   v = lnb[i - OFF_LNB];
    else if (i < OFF_BB)   v = bw[i - OFF_BW];
    else if (i < OFF_BS)   v = bb[i - OFF_BB];
    else if (i < OFF_WW)   v = bs[i - OFF_BS];
    else if (i < OFF_WS)   v = ww[i - OFF_WW];
    else if (i < OFF_PW)   v = ws[i - OFF_WS];
    else if (i < OFF_TLW)  v = pw[i - OFF_PW];
    else if (i < OFF_TLB)  v = tlw[i - OFF_TLW];
    else if (i < OFF_TW)   v = tlb[i - OFF_TLB];
    else if (i < OFF_TB)   v = tw[i - OFF_TW];
    else if (i < OFF_RW)   v = tb[i - OFF_TB];
    else if (i < OFF_RB)   v = rw[i - OFF_RW];
    else if (i < OFF_PREW) v = rb[i - OFF_RB];
    else if (i < OFF_PREB) v = prew[i - OFF_PREW];
    else                   v = preb[i - OFF_PREB];
    g_wpack[i] = v;
}

// ---------------------------------------------------------------------------
// Kernel 1: pre_project  xh[8,16,256,256] -> g_xhp  (weights folded from cW)
// ---------------------------------------------------------------------------
__global__ __launch_bounds__(256) void pre_kernel(const float* __restrict__ xh)
{
    int idx = blockIdx.x * 256 + threadIdx.x;   // covers 8*65536 exactly
    int b   = idx >> 16;
    int pix = idx & 65535;
    const float* px = xh + (size_t)b * 16 * 65536 + pix;
    float in[16];
#pragma unroll
    for (int c = 0; c < 16; c++) in[c] = __ldg(px + (size_t)c * 65536);
#pragma unroll
    for (int o = 0; o < 8; o++) {
        float s = cW[OFF_PREB + o];
#pragma unroll
        for (int c = 0; c < 16; c++) s += cW[OFF_PREW + o * 16 + c] * in[c];
        g_xhp[((size_t)b * 8 + o) * 65536 + pix] = s;
    }
}

// ---------------------------------------------------------------------------
// Per-branch body. Template BR makes every directly-used weight index a
// compile-time constant (folded into FFMA from cW). Wavelet conv weights
// (runtime c,kp indexing) live in smem.
// Block = 256 threads, tile 32x16, each thread owns a vertical pixel pair.
// ---------------------------------------------------------------------------
template<int BR>
__device__ __forceinline__ void do_branch(
    int tid, int x0, int y0, int b,
    const float* __restrict__ xl, const float* __restrict__ mask,
    float (&S)[5][20][36], float4 (&CX4)[5][10][18], float4 (&TAG4)[5][8][16],
    const float* __restrict__ sWW, const float* __restrict__ sWS,
    float* pA, float* pB, float& s1A, float& s2A, float& s1B, float& s2B)
{
    __syncthreads();   // protect S/CX/TAG reuse across branches

    // ---- phase 1: load + bilinear upsample + channel-LN into S ----------
    for (int hp = tid; hp < 720; hp += 256) {
        int sr = hp / 36;
        int sc = hp - sr * 36;
        int y = y0 - 2 + sr, x = x0 - 2 + sc;
        float v0 = 0.f, v1 = 0.f, v2 = 0.f, v3 = 0.f, v4 = 0.f;
        if ((unsigned)y < 512u && (unsigned)x < 512u) {
            const float SC = (float)(255.0 / 511.0);
            float cy = (float)y * SC;
            int   iy = (int)cy; iy = iy > 254 ? 254 : iy;
            float fy = cy - (float)iy;
            float cxx = (float)x * SC;
            int   ix = (int)cxx; ix = ix > 254 ? 254 : ix;
            float fx = cxx - (float)ix;
            float w00 = (1.f - fy) * (1.f - fx);
            float w01 = (1.f - fy) * fx;
            float w10 = fy * (1.f - fx);
            float w11 = fy * fx;
            const float* p0 = g_xhp + (((size_t)b * 8 + 2 * BR) * 256 + iy) * 256 + ix;
            const float* p1 = p0 + 65536;
            v0 = w00 * p0[0] + w01 * p0[1] + w10 * p0[256] + w11 * p0[257];
            v1 = w00 * p1[0] + w01 * p1[1] + w10 * p1[256] + w11 * p1[257];
            size_t xi = (((size_t)b * 8 + 2 * BR) * 512 + y) * 512 + x;
            v2 = __ldg(xl + xi);
            v3 = __ldg(xl + xi + 262144);
            v4 = __ldg(mask + ((size_t)b * 512 + y) * 512 + x);
            float u = 0.2f * (v0 + v1 + v2 + v3 + v4);
            float d0 = v0 - u, d1 = v1 - u, d2 = v2 - u, d3 = v3 - u, d4 = v4 - u;
            float var = 0.2f * (d0 * d0 + d1 * d1 + d2 * d2 + d3 * d3 + d4 * d4);
            float inv = rsqrtf(var + 1e-6f);
            v0 = cW[OFF_LNW + BR * 5 + 0] * (d0 * inv) + cW[OFF_LNB + BR * 5 + 0];
            v1 = cW[OFF_LNW + BR * 5 + 1] * (d1 * inv) + cW[OFF_LNB + BR * 5 + 1];
            v2 = cW[OFF_LNW + BR * 5 + 2] * (d2 * inv) + cW[OFF_LNB + BR * 5 + 2];
            v3 = cW[OFF_LNW + BR * 5 + 3] * (d3 * inv) + cW[OFF_LNB + BR * 5 + 3];
            v4 = cW[OFF_LNW + BR * 5 + 4] * (d4 * inv) + cW[OFF_LNB + BR * 5 + 4];
        }
        S[0][sr][sc] = v0; S[1][sr][sc] = v1; S[2][sr][sc] = v2;
        S[3][sr][sc] = v3; S[4][sr][sc] = v4;
    }
    __syncthreads();

    // ---- phase 2: Haar DWT butterflies -> CX4 ---------------------------
    for (int t = tid; t < 900; t += 256) {
        int c = t / 180; int cell = t - c * 180;
        int ci = cell / 18; int cj = cell - ci * 18;
        int sr = 2 * ci, sc = 2 * cj;
        float2 r0 = *(const float2*)&S[c][sr][sc];
        float2 r1 = *(const float2*)&S[c][sr + 1][sc];
        float su1 = r0.x + r0.y, dd1 = r0.x - r0.y;
        float su2 = r1.x + r1.y, dd2 = r1.x - r1.y;
        CX4[c][ci][cj] = make_float4(0.5f * (su1 + su2),   // LL
                                     0.5f * (su1 - su2),   // LH
                                     0.5f * (dd1 + dd2),   // HL
                                     0.5f * (dd1 - dd2));  // HH
    }
    __syncthreads();

    // ---- phase 3: 3x3 conv on subband pairs, 4-cell quads -> TAG4 -------
    for (int t = tid; t < 320; t += 256) {
        int c  = t >> 6;            // 0..4
        int r  = t & 63;
        int kp = r & 1;             // subband pair: (2kp, 2kp+1)
        int qj = ((r >> 1) & 3) * 4;
        int ti = r >> 3;            // 0..7
        const float* wv = sWW + (((BR * 5 + c) * 4) + 2 * kp) * 9;
        float a0[4] = {0.f, 0.f, 0.f, 0.f};
        float a1[4] = {0.f, 0.f, 0.f, 0.f};
#pragma unroll
        for (int dy = 0; dy < 3; dy++) {
            float2 row[6];
#pragma unroll
            for (int dx = 0; dx < 6; dx++)
                row[dx] = ((const float2*)&CX4[c][ti + dy][qj + dx])[kp];
#pragma unroll
            for (int dx = 0; dx < 3; dx++) {
                float w0 = wv[dy * 3 + dx];
                float w1 = wv[9 + dy * 3 + dx];
#pragma unroll
                for (int cc = 0; cc < 4; cc++) {
                    a0[cc] += w0 * row[cc + dx].x;
                    a1[cc] += w1 * row[cc + dx].y;
                }
            }
        }
        float ws0 = sWS[(BR * 5 + c) * 4 + 2 * kp];
        float ws1 = sWS[(BR * 5 + c) * 4 + 2 * kp + 1];
#pragma unroll
        for (int cc = 0; cc < 4; cc++)
            ((float2*)&TAG4[c][ti][qj + cc])[kp] = make_float2(a0[cc] * ws0, a1[cc] * ws1);
    }
    __syncthreads();

    // ---- phase 4: base conv + iDWT + pointwise for vertical pixel pair --
    {
        int tx = tid & 31, tyh = tid >> 5;   // pixels rows 2tyh, 2tyh+1
        int ci = tyh, cj = tx >> 1;
        int px = tx & 1;
        float o5A[5] = {0.f, 0.f, 0.f, 0.f, 0.f};
        float o5B[5] = {0.f, 0.f, 0.f, 0.f, 0.f};
#pragma unroll
        for (int c = 0; c < 5; c++) {
            // shared 4-row window: rows 2tyh+1 .. 2tyh+4, cols tx+1..tx+3
            float w4[4][3];
#pragma unroll
            for (int dy = 0; dy < 4; dy++)
#pragma unroll
                for (int dx = 0; dx < 3; dx++)
                    w4[dy][dx] = S[c][2 * tyh + 1 + dy][tx + 1 + dx];
            float sA = 0.f, sB = 0.f;
#pragma unroll
            for (int dy = 0; dy < 3; dy++)
#pragma unroll
                for (int dx = 0; dx < 3; dx++) {
                    float wgt = cW[OFF_BW + (BR * 5 + c) * 9 + dy * 3 + dx];
                    sA += wgt * w4[dy][dx];
                    sB += wgt * w4[dy + 1][dx];
                }
            sA = (sA + cW[OFF_BB + BR * 5 + c]) * cW[OFF_BS + BR * 5 + c];
            sB = (sB + cW[OFF_BB + BR * 5 + c]) * cW[OFF_BS + BR * 5 + c];
            float4 tg = TAG4[c][ci][cj];           // shared by both pixels
            float t2 = px ? -tg.z : tg.z;
            // pixel A: py=0 -> +tg.y, t3 sign = px
            float t3A = px ? -tg.w : tg.w;
            float vA = sA + 0.5f * (tg.x + tg.y + t2 + t3A);
            // pixel B: py=1 -> -tg.y, t3 sign = !px
            float t3B = px ? tg.w : -tg.w;
            float vB = sB + 0.5f * (tg.x - tg.y + t2 + t3B);
#pragma unroll
            for (int o = 0; o < 5; o++) {
                float pwv = cW[OFF_PW + BR * 25 + o * 5 + c];
                o5A[o] += pwv * vA;
                o5B[o] += pwv * vB;
            }
        }
#pragma unroll
        for (int jj = 0; jj < 5; jj++) {
            float vA = o5A[jj], vB = o5B[jj];
            s1A += vA; s2A += vA * vA;
            s1B += vB; s2B += vB * vB;
            float vsA = cW[OFF_TLW + BR * 5 + jj] * vA;
            float vsB = cW[OFF_TLW + BR * 5 + jj] * vB;
#pragma unroll
            for (int o = 0; o < 8; o++) {
                float tw = cW[OFF_TW + o * 20 + BR * 5 + jj];
                pA[o] += tw * vsA;
                pB[o] += tw * vsB;
            }
        }
    }
}

// ---------------------------------------------------------------------------
// Kernel 2: fused branches + tail + residual.
// 32x16 tile, 256 threads, vertical pixel pair per thread, 4 blocks/SM.
// ---------------------------------------------------------------------------
__global__ __launch_bounds__(256, 4) void fused_kernel(
    const float* __restrict__ xl,        // [8,8,512,512]
    const float* __restrict__ mask,      // [8,1,512,512]
    const float* __restrict__ g_wt_w,    // [4,20,3,3] (smem copy: runtime idx)
    const float* __restrict__ g_wt_s,    // [4,20]
    float* __restrict__ out)             // [8,8,512,512]
{
    __shared__ float sWW[720];
    __shared__ float sWS[80];
    __shared__ float sRS[8];             // row sums of folded tail matrix
    __shared__ float sC[8];              // folded LN-bias + tail bias
    __shared__ float  S[5][20][36];
    __shared__ float4 CX4[5][10][18];
    __shared__ float4 TAG4[5][8][16];

    const int tid = threadIdx.x;
    for (int t = tid; t < 720; t += 256) sWW[t] = g_wt_w[t];
    for (int t = tid; t < 80;  t += 256) sWS[t] = g_wt_s[t];
    if (tid < 8) {
        float rs = 0.f, C = cW[OFF_TB + tid];
#pragma unroll
        for (int j = 0; j < 20; j++) {
            float w = cW[OFF_TW + tid * 20 + j];
            rs += w * cW[OFF_TLW + j];
            C  += w * cW[OFF_TLB + j];
        }
        sRS[tid] = rs;
        sC[tid]  = C;
    }

    const int x0 = blockIdx.x * 32;
    const int y0 = blockIdx.y * 16;
    const int b  = blockIdx.z;

    float pA[8] = {0.f, 0.f, 0.f, 0.f, 0.f, 0.f, 0.f, 0.f};
    float pB[8] = {0.f, 0.f, 0.f, 0.f, 0.f, 0.f, 0.f, 0.f};
    float s1A = 0.f, s2A = 0.f, s1B = 0.f, s2B = 0.f;

    do_branch<0>(tid, x0, y0, b, xl, mask, S, CX4, TAG4, sWW, sWS, pA, pB, s1A, s2A, s1B, s2B);
    do_branch<1>(tid, x0, y0, b, xl, mask, S, CX4, TAG4, sWW, sWS, pA, pB, s1A, s2A, s1B, s2B);
    do_branch<2>(tid, x0, y0, b, xl, mask, S, CX4, TAG4, sWW, sWS, pA, pB, s1A, s2A, s1B, s2B);
    do_branch<3>(tid, x0, y0, b, xl, mask, S, CX4, TAG4, sWW, sWS, pA, pB, s1A, s2A, s1B, s2B);

    // ---- tail: folded LN(20)+matmul -> exact GELU, + residual -----------
    const int tx = tid & 31, tyh = tid >> 5;
#pragma unroll
    for (int pp = 0; pp < 2; pp++) {
        float* p  = pp ? pB : pA;
        float s1  = pp ? s1B : s1A;
        float s2  = pp ? s2B : s2A;
        float u   = s1 * 0.05f;
        float var = fmaxf(s2 * 0.05f - u * u, 0.f);
        float inv = rsqrtf(var + 1e-6f);

        int y = y0 + 2 * tyh + pp, x = x0 + tx;
        size_t pix = (size_t)y * 512 + x;
        float xv[8];
#pragma unroll
        for (int c = 0; c < 8; c++)
            xv[c] = __ldg(xl + ((size_t)b * 8 + c) * 262144 + pix);
        float mv = __ldg(mask + (size_t)b * 262144 + pix);

#pragma unroll
        for (int o = 0; o < 8; o++) {
            float t = inv * (p[o] - u * sRS[o]) + sC[o];
            float gel = t * 0.5f * (1.f + erff(t * 0.70710678118654752f));
            float r = cW[OFF_RB + o];
#pragma unroll
            for (int c = 0; c < 8; c++) r += cW[OFF_RW + o * 9 + c] * xv[c];
            r += cW[OFF_RW + o * 9 + 8] * mv;
            out[((size_t)b * 8 + o) * 262144 + pix] = gel + r;
        }
    }
}

// ---------------------------------------------------------------------------
// kernel_launch
// Inputs: 0 xh, 1 xl, 2 mask, 3 pre_w, 4 pre_b, 5 g_ln_w, 6 g_ln_b,
//  7 g_base_w, 8 g_base_b, 9 g_base_s, 10 g_wt_w, 11 g_wt_s, 12 g_pw_w,
// 13 tail_ln_w, 14 tail_ln_b, 15 tail_w, 16 tail_b, 17 res_w, 18 res_b
// ---------------------------------------------------------------------------
extern "C" void kernel_launch(void* const* d_in, const int* in_sizes, int n_in,
                              void* d_out, int out_size)
{
    (void)in_sizes; (void)n_in; (void)out_size;
    const float* xh   = (const float*)d_in[0];
    const float* xl   = (const float*)d_in[1];
    const float* mask = (const float*)d_in[2];
    float* out = (float*)d_out;

    pack_kernel<<<(W_TOTAL + 255) / 256, 256>>>(
        (const float*)d_in[5],  (const float*)d_in[6],
        (const float*)d_in[7],  (const float*)d_in[8],
        (const float*)d_in[9],  (const float*)d_in[10],
        (const float*)d_in[11], (const float*)d_in[12],
        (const float*)d_in[13], (const float*)d_in[14],
        (const float*)d_in[15], (const float*)d_in[16],
        (const float*)d_in[17], (const float*)d_in[18],
        (const float*)d_in[3],  (const float*)d_in[4]);

    void* wpack_ptr = nullptr;
    cudaGetSymbolAddress(&wpack_ptr, g_wpack);
    cudaMemcpyToSymbolAsync(cW, wpack_ptr, W_TOTAL * sizeof(float), 0,
                            cudaMemcpyDeviceToDevice, 0);

    pre_kernel<<<2048, 256>>>(xh);

    dim3 grid(512 / 32, 512 / 16, 8);   // 16 x 32 x 8 tiles
    fused_kernel<<<grid, 256>>>(xl, mask,
                                (const float*)d_in[10], (const float*)d_in[11],
                                out);
}